// round 8
// baseline (speedup 1.0000x reference)
#include <cuda_runtime.h>
#include <cuda_fp16.h>
#include <cstdint>

// ---------------- problem constants ----------------
#define NB    883
#define BTI   96
#define TOT   (NB*BTI)       // 84768
#define DIM   128
#define FFD   2048
#define EMAX  7168

// ---------------- device scratch ----------------
__device__ float g_agg [(size_t)TOT*DIM];
__device__ float g_agg2[(size_t)TOT*DIM];
__device__ float g_h  [(size_t)TOT*DIM];
__device__ __half g_hb [(size_t)TOT*DIM];    // h fp16
__device__ float g_ff1[(size_t)TOT*FFD/2];   // xlr fp16 (TOT*256) early; ff1 fp16 (TOT*2048) later
__device__ __half g_xb [(size_t)TOT*DIM];    // x fp16
__device__ __half g_wlrt[256*DIM];           // [Wl;Wr] transposed: [256, 128]
__device__ __half g_w1t[(size_t)FFD*DIM];    // W1^T [2048,128]
__device__ __half g_w2t[(size_t)DIM*FFD];    // W2^T [128,2048]
__device__ float  g_blr[256];

__device__ int g_src[EMAX];
__device__ int g_dst[EMAX];
__device__ int g_deg[NB];
__device__ int g_rowptr[NB+1];
__device__ int g_wp[NB];
__device__ int g_csr[EMAX+NB];
__device__ int g_flag;   // sticky across replays: OR-idempotent => deterministic

// ---------------- helpers ----------------
__device__ __forceinline__ uint32_t smem_u32(const void* p) {
    uint32_t a;
    asm("{ .reg .u64 t; cvta.to.shared.u64 t, %1; cvt.u32.u64 %0, t; }" : "=r"(a) : "l"(p));
    return a;
}
__device__ __forceinline__ void cp16(uint32_t s, const void* g) {
    asm volatile("cp.async.cg.shared.global [%0], [%1], 16;" :: "r"(s), "l"(g));
}
#define CP_COMMIT() asm volatile("cp.async.commit_group;" ::: "memory")
#define CP_WAIT1()  asm volatile("cp.async.wait_group 1;" ::: "memory")

__device__ __forceinline__ void ldm4(uint32_t* r, uint32_t addr) {
    asm volatile("ldmatrix.sync.aligned.m8n8.x4.shared.b16 {%0,%1,%2,%3}, [%4];"
        : "=r"(r[0]), "=r"(r[1]), "=r"(r[2]), "=r"(r[3]) : "r"(addr));
}
__device__ __forceinline__ void mma16816(float* d, const uint32_t* a, const uint32_t* b) {
    asm volatile(
        "mma.sync.aligned.m16n8k16.row.col.f32.f16.f16.f32 "
        "{%0,%1,%2,%3}, {%4,%5,%6,%7}, {%8,%9}, {%0,%1,%2,%3};"
        : "+f"(d[0]), "+f"(d[1]), "+f"(d[2]), "+f"(d[3])
        : "r"(a[0]), "r"(a[1]), "r"(a[2]), "r"(a[3]), "r"(b[0]), "r"(b[1]));
}

// ==================================================================================
// fp16 GEMM via mma.sync: C[M,N] = A[M,K] @ B[N,K]^T
// BM=128, BN=128, BK=32, 3-stage cp.async, 512 threads, 16 warps of 32x32 tiles,
// single __syncthreads per k-iter, 2 CTA/SM (50% occ).
// gridDim.z==2 => split-K: z selects K-half; z=0 -> C (+bias), z=1 -> C2 (no bias).
// ==================================================================================
#define SROWB   80
#define ARRB    (128*SROWB)
#define STAGEB  (2*ARRB)
#define GSMEM   (3*STAGEB)           // 61440

__global__ void __launch_bounds__(512, 2) mmagemm(
    const __half* __restrict__ A, const __half* __restrict__ B,
    const float* __restrict__ bias, float* __restrict__ C, float* __restrict__ C2,
    __half* __restrict__ Oh,
    int M, int N, int K, int lda, int ldb, int relu)
{
    extern __shared__ char smem[];
    const uint32_t sb = smem_u32(smem);
    const int tid = threadIdx.x;
    const int lane = tid & 31, wid = tid >> 5;
    const int wm = wid & 3, wn = wid >> 2;       // 4x4 warp grid
    const int bm = blockIdx.x * 128, bn = blockIdx.y * 128;
    const int nk = K >> 5;

    // split-K via z
    if (blockIdx.z) {
        A += (size_t)blockIdx.z * K;
        B += (size_t)blockIdx.z * K;
        C = C2;
        bias = nullptr;
    }

    auto load_stage = [&](int st, int kc) {
        int k0 = kc << 5;
        uint32_t base = sb + st * STAGEB;
#pragma unroll
        for (int j = 0; j < 2; j++) {
            int id = tid + 512 * j;
            int arr = id >> 9;            // 0=A 1=B
            int c = id & 511;
            int row = c >> 2, col = c & 3;
            const __half* g;
            if (arr == 0) g = A + (size_t)min(bm + row, M - 1) * lda + k0 + col * 8;
            else          g = B + (size_t)(bn + row) * ldb + k0 + col * 8;
            cp16(base + arr * ARRB + row * SROWB + col * 16, g);
        }
        CP_COMMIT();
    };

    float acc[2][4][4];
#pragma unroll
    for (int mi = 0; mi < 2; mi++)
#pragma unroll
        for (int ni = 0; ni < 4; ni++)
#pragma unroll
            for (int q = 0; q < 4; q++) acc[mi][ni][q] = 0.f;

    const uint32_t aoff = (uint32_t)((wm * 32 + (lane & 15)) * SROWB + ((lane >> 4) * 16));
    const uint32_t boff = (uint32_t)((wn * 32 + (lane & 7) + ((lane >> 4) << 3)) * SROWB
                                     + (((lane >> 3) & 1) * 16));

    load_stage(0, 0);
    load_stage(1, 1);

    for (int c = 0; c < nk; c++) {
        CP_WAIT1();
        __syncthreads();        // single barrier per iter: also protects stage reuse
        if (c + 2 < nk) load_stage((c + 2) % 3, c + 2);
        else CP_COMMIT();

        uint32_t s = sb + (c % 3) * STAGEB;
        uint32_t sA = s, sB = s + ARRB;
#pragma unroll
        for (int kk = 0; kk < 2; kk++) {
            uint32_t kb = kk * 32;
            uint32_t af[2][4], bf[2][4];
#pragma unroll
            for (int mi = 0; mi < 2; mi++)
                ldm4(af[mi], sA + aoff + mi * (16 * SROWB) + kb);
#pragma unroll
            for (int p = 0; p < 2; p++)
                ldm4(bf[p], sB + boff + p * (16 * SROWB) + kb);
#pragma unroll
            for (int mi = 0; mi < 2; mi++)
#pragma unroll
                for (int ni = 0; ni < 4; ni++)
                    mma16816(acc[mi][ni], af[mi], &bf[ni >> 1][(ni & 1) * 2]);
        }
    }

    // epilogue (no trailing sync needed: last iter's compute precedes this per-warp)
#pragma unroll
    for (int mi = 0; mi < 2; mi++) {
#pragma unroll
        for (int ni = 0; ni < 4; ni++) {
            int row0 = bm + wm * 32 + mi * 16 + (lane >> 2);
            int col  = bn + wn * 32 + ni * 8 + (lane & 3) * 2;
            float b0 = bias ? __ldg(bias + col)     : 0.f;
            float b1 = bias ? __ldg(bias + col + 1) : 0.f;
#pragma unroll
            for (int half_ = 0; half_ < 2; half_++) {
                int row = row0 + half_ * 8;
                if (row >= M) continue;
                float v0 = acc[mi][ni][half_ * 2 + 0] + b0;
                float v1 = acc[mi][ni][half_ * 2 + 1] + b1;
                if (relu) { v0 = fmaxf(v0, 0.f); v1 = fmaxf(v1, 0.f); }
                if (C)
                    *(float2*)(C + (size_t)row * N + col) = make_float2(v0, v1);
                if (Oh) {
                    __half2 hh; hh.x = __float2half(v0); hh.y = __float2half(v1);
                    *(__half2*)(Oh + (size_t)row * N + col) = hh;
                }
            }
        }
    }
}

// ---------------- merged prelude kernels ----------------
__global__ void k_init_detect(const int* __restrict__ w, int E) {
    int k = blockIdx.x * blockDim.x + threadIdx.x;
    if (k < NB) g_deg[k] = 1;                     // self loop
    if (k < E && w[2 * k + 1] != 0) atomicOr(&g_flag, 1);
}
__global__ void k_decode_hist(const int* __restrict__ w, int E) {
    int k = blockIdx.x * blockDim.x + threadIdx.x;
    if (k >= E) return;
    int s, d;
    if (g_flag == 0) { s = w[2 * k]; d = w[2 * (E + k)]; }
    else             { s = w[k];     d = w[E + k]; }
    g_src[k] = s;
    g_dst[k] = d;
    atomicAdd(&g_deg[d], 1);
}
__global__ void k_cvt_all(const float* __restrict__ x,
                          const float* __restrict__ Wl, const float* __restrict__ Wr,
                          const float* __restrict__ W1, const float* __restrict__ W2,
                          const float* __restrict__ bl, const float* __restrict__ br)
{
    const long N0 = (long)TOT * DIM / 4;
    long id = (long)blockIdx.x * blockDim.x + threadIdx.x;
    if (id < N0) {
        float4 v = ((const float4*)x)[id];
        long s = id * 4;
        __half2 a; a.x = __float2half(v.x); a.y = __float2half(v.y);
        __half2 b; b.x = __float2half(v.z); b.y = __float2half(v.w);
        *(__half2*)(g_xb + s)     = a;
        *(__half2*)(g_xb + s + 2) = b;
        return;
    }
    id -= N0;
    if (id < DIM * DIM) {
        int k = (int)id / DIM, n = (int)id % DIM;
        g_wlrt[(size_t)n * DIM + k] = __float2half(Wl[id]);
        return;
    }
    id -= DIM * DIM;
    if (id < DIM * DIM) {
        int k = (int)id / DIM, n = (int)id % DIM;
        g_wlrt[(size_t)(128 + n) * DIM + k] = __float2half(Wr[id]);
        return;
    }
    id -= DIM * DIM;
    if (id < (long)DIM * FFD) {
        int k = (int)(id / FFD), n = (int)(id % FFD);
        g_w1t[(size_t)n * DIM + k] = __float2half(W1[id]);
        return;
    }
    id -= (long)DIM * FFD;
    if (id < (long)DIM * FFD) {
        int k = (int)(id / DIM), n = (int)(id % DIM);
        g_w2t[(size_t)n * FFD + k] = __float2half(W2[id]);
        return;
    }
    id -= (long)DIM * FFD;
    if (id < 256) {
        g_blr[id] = (id < 128) ? bl[id] : br[id - 128];
    }
}

__global__ void k_scan() {
    __shared__ int s[1024];
    int t = threadIdx.x;
    int v = (t < NB) ? g_deg[t] : 0;
    s[t] = v;
    __syncthreads();
    for (int off = 1; off < 1024; off <<= 1) {
        int u = (t >= off) ? s[t - off] : 0;
        __syncthreads();
        s[t] += u;
        __syncthreads();
    }
    if (t < NB) { g_rowptr[t + 1] = s[t]; g_wp[t] = s[t] - v; }
    if (t == 0) g_rowptr[0] = 0;
}
__global__ void k_scatter(int E) {
    int j = blockIdx.x * blockDim.x + threadIdx.x;
    if (j >= E + NB) return;
    int s, d;
    if (j < E) { s = g_src[j]; d = g_dst[j]; }
    else       { s = d = j - E; }
    g_csr[atomicAdd(&g_wp[d], 1)] = s;
}

// ---------------- fused GATv2 edge aggregation + LN1 ----------------
__global__ void __launch_bounds__(256) k_edge_ln1(
    const __half* __restrict__ xlr, const float* __restrict__ x,
    const float* __restrict__ att, const float* __restrict__ bias_gat,
    const float* __restrict__ gamma, const float* __restrict__ beta,
    float* __restrict__ hout, __half* __restrict__ hhout)
{
    __shared__ float redS[4][2], redQ[4][2];
    const int i = blockIdx.x;
    const int gidx = threadIdx.x >> 6;
    const int t2 = threadIdx.x & 63;
    const int b = blockIdx.y * 4 + gidx;
    const int g = b * NB + i;
    const int base = b * NB;

    float2 attv = *(const float2*)(att + 2 * t2);
    __half2 rx2 = *(const __half2*)(xlr + (size_t)g * 256 + 128 + 2 * t2);
    float rx0 = __half2float(rx2.x), rx1 = __half2float(rx2.y);

    const int e0 = g_rowptr[i], e1 = g_rowptr[i + 1];
    float ss = 0.f, a0 = 0.f, a1 = 0.f;
#pragma unroll 2
    for (int e = e0; e < e1; e++) {
        int sg = base + g_csr[e];
        __half2 v2 = *(const __half2*)(xlr + (size_t)sg * 256 + 2 * t2);
        float v0 = __half2float(v2.x), v1 = __half2float(v2.y);
        float e0f = v0 + rx0, e1f = v1 + rx1;
        e0f = e0f > 0.f ? e0f : 0.2f * e0f;
        e1f = e1f > 0.f ? e1f : 0.2f * e1f;
        float p = e0f * attv.x + e1f * attv.y;
        p += __shfl_xor_sync(0xffffffffu, p, 4, 8);
        p += __shfl_xor_sync(0xffffffffu, p, 2, 8);
        p += __shfl_xor_sync(0xffffffffu, p, 1, 8);
        float w = __expf(p);
        ss += w;
        a0 += w * v0;
        a1 += w * v1;
    }
    float2 bg2 = *(const float2*)(bias_gat + 2 * t2);
    float inv = 1.f / ss;
    float r0 = a0 * inv + bg2.x;
    float r1 = a1 * inv + bg2.y;

    float2 xv = *(const float2*)(x + (size_t)g * DIM + 2 * t2);
    float v0 = xv.x + r0, v1 = xv.y + r1;

    int wg = t2 >> 5, lane = t2 & 31;
    float s = v0 + v1;
#pragma unroll
    for (int o = 16; o >= 1; o >>= 1) s += __shfl_xor_sync(0xffffffffu, s, o);
    if (lane == 0) redS[gidx][wg] = s;
    __syncthreads();
    float mu = (redS[gidx][0] + redS[gidx][1]) * (1.f / DIM);
    float d0 = v0 - mu, d1 = v1 - mu;
    float q = d0 * d0 + d1 * d1;
#pragma unroll
    for (int o = 16; o >= 1; o >>= 1) q += __shfl_xor_sync(0xffffffffu, q, o);
    if (lane == 0) redQ[gidx][wg] = q;
    __syncthreads();
    float var = (redQ[gidx][0] + redQ[gidx][1]) * (1.f / DIM);
    float rstd = rsqrtf(var + 1e-5f);
    float2 gm = *(const float2*)(gamma + 2 * t2);
    float2 be = *(const float2*)(beta  + 2 * t2);
    float h0 = d0 * rstd * gm.x + be.x;
    float h1 = d1 * rstd * gm.y + be.y;
    *(float2*)(hout + (size_t)g * DIM + 2 * t2) = make_float2(h0, h1);
    __half2 hh; hh.x = __float2half(h0); hh.y = __float2half(h1);
    *(__half2*)(hhout + (size_t)g * DIM + 2 * t2) = hh;
}

// ---------------- LN2: out = LN(h + agg + agg2) ----------------
__global__ void k_ln3(const float* __restrict__ A, const float* __restrict__ B1,
                      const float* __restrict__ B2,
                      const float* __restrict__ gamma, const float* __restrict__ beta,
                      float* __restrict__ out)
{
    int g = blockIdx.x, t = threadIdx.x;
    size_t idx = (size_t)g * DIM + t;
    float v = A[idx] + B1[idx] + B2[idx];
    __shared__ float red[4];
    int lane = t & 31, w = t >> 5;
    float s = v;
#pragma unroll
    for (int o = 16; o >= 1; o >>= 1) s += __shfl_xor_sync(0xffffffffu, s, o);
    if (lane == 0) red[w] = s;
    __syncthreads();
    float mu = (red[0] + red[1] + red[2] + red[3]) * (1.f / DIM);
    float d = v - mu;
    float q = d * d;
#pragma unroll
    for (int o = 16; o >= 1; o >>= 1) q += __shfl_xor_sync(0xffffffffu, q, o);
    __syncthreads();
    if (lane == 0) red[w] = q;
    __syncthreads();
    float var = (red[0] + red[1] + red[2] + red[3]) * (1.f / DIM);
    out[idx] = d * rsqrtf(var + 1e-5f) * gamma[t] + beta[t];
}

// ---------------- launcher ----------------
extern "C" void kernel_launch(void* const* d_in, const int* in_sizes, int n_in,
                              void* d_out, int out_size)
{
    const float* x   = (const float*)d_in[0];
    const int*   ei  = (const int*)  d_in[1];
    const float* Wl  = (const float*)d_in[2];
    const float* bl  = (const float*)d_in[3];
    const float* Wr  = (const float*)d_in[4];
    const float* brv = (const float*)d_in[5];
    const float* att = (const float*)d_in[6];
    const float* bg  = (const float*)d_in[7];
    const float* W1  = (const float*)d_in[8];
    const float* b1  = (const float*)d_in[9];
    const float* W2  = (const float*)d_in[10];
    const float* b2  = (const float*)d_in[11];
    const float* g1  = (const float*)d_in[12];
    const float* be1 = (const float*)d_in[13];
    const float* g2  = (const float*)d_in[14];
    const float* be2 = (const float*)d_in[15];
    float* out = (float*)d_out;

    int E = in_sizes[1] / 2;
    if (E > EMAX) E = EMAX;

    cudaFuncSetAttribute(mmagemm, cudaFuncAttributeMaxDynamicSharedMemorySize, GSMEM);

    void *pagg, *pagg2, *ph, *phb, *pff1, *pxb, *pwlrt, *pw1t, *pw2t, *pblr;
    cudaGetSymbolAddress(&pagg,  g_agg);
    cudaGetSymbolAddress(&pagg2, g_agg2);
    cudaGetSymbolAddress(&ph,    g_h);
    cudaGetSymbolAddress(&phb,   g_hb);
    cudaGetSymbolAddress(&pff1,  g_ff1);
    cudaGetSymbolAddress(&pxb,   g_xb);
    cudaGetSymbolAddress(&pwlrt, g_wlrt);
    cudaGetSymbolAddress(&pw1t,  g_w1t);
    cudaGetSymbolAddress(&pw2t,  g_w2t);
    cudaGetSymbolAddress(&pblr,  g_blr);

    __half* xb   = (__half*)pxb;
    __half* wlrt = (__half*)pwlrt;
    __half* w1t  = (__half*)pw1t;
    __half* w2t  = (__half*)pw2t;
    __half* hh   = (__half*)phb;
    __half* xlr  = (__half*)pff1;       // [TOT,256] fp16, dead after k_edge_ln1
    __half* ff1  = (__half*)pff1;       // [TOT,2048] fp16, written after xlr dead

    const int GM = (TOT + 127) / 128;   // 663
    const long NCVT = (long)TOT * DIM / 4 + 2L * DIM * DIM + 2L * DIM * FFD + 256;
    const int GCVT = (int)((NCVT + 255) / 256);
    int gE = (E + 255) / 256;

    // 1-2: edge decode + degree histogram
    k_init_detect<<<gE, 256>>>(ei, E);
    k_decode_hist<<<gE, 256>>>(ei, E);
    // 3: all conversions
    k_cvt_all<<<GCVT, 256>>>(x, Wl, Wr, W1, W2, bl, brv);
    // 4: [x_l | x_r] = x @ [Wl|Wr] + [bl|br]
    mmagemm<<<dim3(GM, 2, 1), 512, GSMEM>>>(xb, wlrt, (const float*)pblr,
        nullptr, nullptr, xlr, TOT, 256, DIM, DIM, DIM, 0);
    // 5-6: CSR finalize
    k_scan<<<1, 1024>>>();
    k_scatter<<<(E + NB + 255) / 256, 256>>>(E);
    // 7: GATv2 aggregation + LN1 fused -> h (fp32 + fp16)
    k_edge_ln1<<<dim3(NB, BTI / 4), 256>>>(xlr, x, att, bg, g1, be1, (float*)ph, hh);
    // 8: ff1 = relu(h@W1 + b1) -> fp16
    mmagemm<<<dim3(GM, 16, 1), 512, GSMEM>>>(hh, w1t, b1,
        nullptr, nullptr, ff1, TOT, FFD, DIM, DIM, DIM, 1);
    // 9: ffn = ff1@W2 + b2, split-K fused in one launch (z selects K-half)
    mmagemm<<<dim3(GM, 1, 2), 512, GSMEM>>>(ff1, w2t, b2,
        (float*)pagg, (float*)pagg2, nullptr, TOT, DIM, 1024, FFD, FFD, 0);
    // 10: out = LN2(h + ffn halves)
    k_ln3<<<TOT, 128>>>((const float*)ph, (const float*)pagg, (const float*)pagg2,
                        g2, be2, out);
}

// round 9
// speedup vs baseline: 1.5751x; 1.5751x over previous
#include <cuda_runtime.h>
#include <cuda_fp16.h>
#include <cstdint>

// ---------------- problem constants ----------------
#define NB    883
#define BTI   96
#define TOT   (NB*BTI)       // 84768
#define DIM   128
#define FFD   2048
#define EMAX  7168

// ---------------- device scratch ----------------
__device__ float g_agg [(size_t)TOT*DIM];
__device__ float g_agg2[(size_t)TOT*DIM];
__device__ float g_h  [(size_t)TOT*DIM];
__device__ __half g_hb [(size_t)TOT*DIM];    // h fp16
__device__ float g_ff1[(size_t)TOT*FFD/2];   // xlr fp16 (TOT*256) early; ff1 fp16 (TOT*2048) later
__device__ __half g_xb [(size_t)TOT*DIM];    // x fp16
__device__ __half g_wlrt[256*DIM];           // [Wl;Wr] transposed: [256, 128]
__device__ __half g_w1t[(size_t)FFD*DIM];    // W1^T [2048,128]
__device__ __half g_w2t[(size_t)DIM*FFD];    // W2^T [128,2048]
__device__ float  g_blr[256];

__device__ int g_src[EMAX];
__device__ int g_dst[EMAX];
__device__ int g_deg[NB];
__device__ int g_rowptr[NB+1];
__device__ int g_wp[NB];
__device__ int g_csr[EMAX+NB];
__device__ int g_flag;   // sticky across replays: OR-idempotent => deterministic

// ---------------- helpers ----------------
__device__ __forceinline__ uint32_t smem_u32(const void* p) {
    uint32_t a;
    asm("{ .reg .u64 t; cvta.to.shared.u64 t, %1; cvt.u32.u64 %0, t; }" : "=r"(a) : "l"(p));
    return a;
}
__device__ __forceinline__ void cp16(uint32_t s, const void* g) {
    asm volatile("cp.async.cg.shared.global [%0], [%1], 16;" :: "r"(s), "l"(g));
}
#define CP_COMMIT() asm volatile("cp.async.commit_group;" ::: "memory")
#define CP_WAIT1()  asm volatile("cp.async.wait_group 1;" ::: "memory")

__device__ __forceinline__ void ldm4(uint32_t* r, uint32_t addr) {
    asm volatile("ldmatrix.sync.aligned.m8n8.x4.shared.b16 {%0,%1,%2,%3}, [%4];"
        : "=r"(r[0]), "=r"(r[1]), "=r"(r[2]), "=r"(r[3]) : "r"(addr));
}
__device__ __forceinline__ void mma16816(float* d, const uint32_t* a, const uint32_t* b) {
    asm volatile(
        "mma.sync.aligned.m16n8k16.row.col.f32.f16.f16.f32 "
        "{%0,%1,%2,%3}, {%4,%5,%6,%7}, {%8,%9}, {%0,%1,%2,%3};"
        : "+f"(d[0]), "+f"(d[1]), "+f"(d[2]), "+f"(d[3])
        : "r"(a[0]), "r"(a[1]), "r"(a[2]), "r"(a[3]), "r"(b[0]), "r"(b[1]));
}

// ==================================================================================
// fp16 GEMM via mma.sync: C[M,N] = A[M,K] @ B[N,K]^T
// R7 tiling restored: BM=128, BN=128, 256 threads, 8 warps of 32x64 tiles, 2 CTA/SM.
// New: BK=64 with 2-stage double-buffer (half the barriers of BK=32 x 3-stage).
// gridDim.z==2 => split-K: z selects K-half; z=0 -> C (+bias), z=1 -> C2 (no bias).
// ==================================================================================
#define SROWB   144                  // 128B data + 16B pad (16r mod 128 -> conflict-free)
#define ARRB    (128*SROWB)          // 18432
#define STAGEB  (2*ARRB)             // 36864
#define GSMEM   (2*STAGEB)           // 73728

__global__ void __launch_bounds__(256, 2) mmagemm(
    const __half* __restrict__ A, const __half* __restrict__ B,
    const float* __restrict__ bias, float* __restrict__ C, float* __restrict__ C2,
    __half* __restrict__ Oh,
    int M, int N, int K, int lda, int ldb, int relu)
{
    extern __shared__ char smem[];
    const uint32_t sb = smem_u32(smem);
    const int tid = threadIdx.x;
    const int lane = tid & 31, wid = tid >> 5;
    const int wm = wid & 3, wn = wid >> 2;       // 4x2 warp grid, 32x64 tiles
    const int bm = blockIdx.x * 128, bn = blockIdx.y * 128;
    const int nk = K >> 6;                        // BK=64

    if (blockIdx.z) {                             // split-K
        A += (size_t)blockIdx.z * K;
        B += (size_t)blockIdx.z * K;
        C = C2;
        bias = nullptr;
    }

    auto load_stage = [&](int st, int kc) {
        int k0 = kc << 6;
        uint32_t base = sb + st * STAGEB;
#pragma unroll
        for (int j = 0; j < 8; j++) {
            int id = tid + 256 * j;
            int arr = id >> 10;           // 0=A 1=B (1024 chunks each)
            int c = id & 1023;
            int row = c >> 3, col = c & 7;
            const __half* g;
            if (arr == 0) g = A + (size_t)min(bm + row, M - 1) * lda + k0 + col * 8;
            else          g = B + (size_t)(bn + row) * ldb + k0 + col * 8;
            cp16(base + arr * ARRB + row * SROWB + col * 16, g);
        }
        CP_COMMIT();
    };

    float acc[2][8][4];
#pragma unroll
    for (int mi = 0; mi < 2; mi++)
#pragma unroll
        for (int ni = 0; ni < 8; ni++)
#pragma unroll
            for (int q = 0; q < 4; q++) acc[mi][ni][q] = 0.f;

    const uint32_t aoff = (uint32_t)((wm * 32 + (lane & 15)) * SROWB + ((lane >> 4) * 16));
    const uint32_t boff = (uint32_t)((wn * 64 + (lane & 7) + ((lane >> 4) << 3)) * SROWB
                                     + (((lane >> 3) & 1) * 16));

    load_stage(0, 0);

    for (int c = 0; c < nk; c++) {
        if (c + 1 < nk) load_stage((c + 1) & 1, c + 1);
        else CP_COMMIT();
        CP_WAIT1();              // stage c resident; stage c+1 may still be in flight
        __syncthreads();

        uint32_t s = sb + (c & 1) * STAGEB;
        uint32_t sA = s, sB = s + ARRB;
#pragma unroll
        for (int kk = 0; kk < 4; kk++) {
            uint32_t kb = kk * 32;
            uint32_t af[2][4], bf[4][4];
#pragma unroll
            for (int mi = 0; mi < 2; mi++)
                ldm4(af[mi], sA + aoff + mi * (16 * SROWB) + kb);
#pragma unroll
            for (int p = 0; p < 4; p++)
                ldm4(bf[p], sB + boff + p * (16 * SROWB) + kb);
#pragma unroll
            for (int mi = 0; mi < 2; mi++)
#pragma unroll
                for (int ni = 0; ni < 8; ni++)
                    mma16816(acc[mi][ni], af[mi], &bf[ni >> 1][(ni & 1) * 2]);
        }
        __syncthreads();         // protect buffer (c+1)&1 before next iter's load
    }

    // epilogue
#pragma unroll
    for (int mi = 0; mi < 2; mi++) {
#pragma unroll
        for (int ni = 0; ni < 8; ni++) {
            int row0 = bm + wm * 32 + mi * 16 + (lane >> 2);
            int col  = bn + wn * 64 + ni * 8 + (lane & 3) * 2;
            float b0 = bias ? __ldg(bias + col)     : 0.f;
            float b1 = bias ? __ldg(bias + col + 1) : 0.f;
#pragma unroll
            for (int half_ = 0; half_ < 2; half_++) {
                int row = row0 + half_ * 8;
                if (row >= M) continue;
                float v0 = acc[mi][ni][half_ * 2 + 0] + b0;
                float v1 = acc[mi][ni][half_ * 2 + 1] + b1;
                if (relu) { v0 = fmaxf(v0, 0.f); v1 = fmaxf(v1, 0.f); }
                if (C)
                    *(float2*)(C + (size_t)row * N + col) = make_float2(v0, v1);
                if (Oh) {
                    __half2 hh; hh.x = __float2half(v0); hh.y = __float2half(v1);
                    *(__half2*)(Oh + (size_t)row * N + col) = hh;
                }
            }
        }
    }
}

// ---------------- merged prelude kernels ----------------
__global__ void k_init_detect(const int* __restrict__ w, int E) {
    int k = blockIdx.x * blockDim.x + threadIdx.x;
    if (k < NB) g_deg[k] = 1;                     // self loop
    if (k < E && w[2 * k + 1] != 0) atomicOr(&g_flag, 1);
}
__global__ void k_decode_hist(const int* __restrict__ w, int E) {
    int k = blockIdx.x * blockDim.x + threadIdx.x;
    if (k >= E) return;
    int s, d;
    if (g_flag == 0) { s = w[2 * k]; d = w[2 * (E + k)]; }
    else             { s = w[k];     d = w[E + k]; }
    g_src[k] = s;
    g_dst[k] = d;
    atomicAdd(&g_deg[d], 1);
}
__global__ void k_cvt_all(const float* __restrict__ x,
                          const float* __restrict__ Wl, const float* __restrict__ Wr,
                          const float* __restrict__ W1, const float* __restrict__ W2,
                          const float* __restrict__ bl, const float* __restrict__ br)
{
    const long N0 = (long)TOT * DIM / 4;
    long id = (long)blockIdx.x * blockDim.x + threadIdx.x;
    if (id < N0) {
        float4 v = ((const float4*)x)[id];
        long s = id * 4;
        __half2 a; a.x = __float2half(v.x); a.y = __float2half(v.y);
        __half2 b; b.x = __float2half(v.z); b.y = __float2half(v.w);
        *(__half2*)(g_xb + s)     = a;
        *(__half2*)(g_xb + s + 2) = b;
        return;
    }
    id -= N0;
    if (id < DIM * DIM) {
        int k = (int)id / DIM, n = (int)id % DIM;
        g_wlrt[(size_t)n * DIM + k] = __float2half(Wl[id]);
        return;
    }
    id -= DIM * DIM;
    if (id < DIM * DIM) {
        int k = (int)id / DIM, n = (int)id % DIM;
        g_wlrt[(size_t)(128 + n) * DIM + k] = __float2half(Wr[id]);
        return;
    }
    id -= DIM * DIM;
    if (id < (long)DIM * FFD) {
        int k = (int)(id / FFD), n = (int)(id % FFD);
        g_w1t[(size_t)n * DIM + k] = __float2half(W1[id]);
        return;
    }
    id -= (long)DIM * FFD;
    if (id < (long)DIM * FFD) {
        int k = (int)(id / DIM), n = (int)(id % DIM);
        g_w2t[(size_t)n * FFD + k] = __float2half(W2[id]);
        return;
    }
    id -= (long)DIM * FFD;
    if (id < 256) {
        g_blr[id] = (id < 128) ? bl[id] : br[id - 128];
    }
}

__global__ void k_scan() {
    __shared__ int s[1024];
    int t = threadIdx.x;
    int v = (t < NB) ? g_deg[t] : 0;
    s[t] = v;
    __syncthreads();
    for (int off = 1; off < 1024; off <<= 1) {
        int u = (t >= off) ? s[t - off] : 0;
        __syncthreads();
        s[t] += u;
        __syncthreads();
    }
    if (t < NB) { g_rowptr[t + 1] = s[t]; g_wp[t] = s[t] - v; }
    if (t == 0) g_rowptr[0] = 0;
}
__global__ void k_scatter(int E) {
    int j = blockIdx.x * blockDim.x + threadIdx.x;
    if (j >= E + NB) return;
    int s, d;
    if (j < E) { s = g_src[j]; d = g_dst[j]; }
    else       { s = d = j - E; }
    g_csr[atomicAdd(&g_wp[d], 1)] = s;
}

// ---------------- fused GATv2 edge aggregation + LN1 ----------------
__global__ void __launch_bounds__(256) k_edge_ln1(
    const __half* __restrict__ xlr, const float* __restrict__ x,
    const float* __restrict__ att, const float* __restrict__ bias_gat,
    const float* __restrict__ gamma, const float* __restrict__ beta,
    float* __restrict__ hout, __half* __restrict__ hhout)
{
    __shared__ float redS[4][2], redQ[4][2];
    const int i = blockIdx.x;
    const int gidx = threadIdx.x >> 6;
    const int t2 = threadIdx.x & 63;
    const int b = blockIdx.y * 4 + gidx;
    const int g = b * NB + i;
    const int base = b * NB;

    float2 attv = *(const float2*)(att + 2 * t2);
    __half2 rx2 = *(const __half2*)(xlr + (size_t)g * 256 + 128 + 2 * t2);
    float rx0 = __half2float(rx2.x), rx1 = __half2float(rx2.y);

    const int e0 = g_rowptr[i], e1 = g_rowptr[i + 1];
    float ss = 0.f, a0 = 0.f, a1 = 0.f;
#pragma unroll 2
    for (int e = e0; e < e1; e++) {
        int sg = base + g_csr[e];
        __half2 v2 = *(const __half2*)(xlr + (size_t)sg * 256 + 2 * t2);
        float v0 = __half2float(v2.x), v1 = __half2float(v2.y);
        float e0f = v0 + rx0, e1f = v1 + rx1;
        e0f = e0f > 0.f ? e0f : 0.2f * e0f;
        e1f = e1f > 0.f ? e1f : 0.2f * e1f;
        float p = e0f * attv.x + e1f * attv.y;
        p += __shfl_xor_sync(0xffffffffu, p, 4, 8);
        p += __shfl_xor_sync(0xffffffffu, p, 2, 8);
        p += __shfl_xor_sync(0xffffffffu, p, 1, 8);
        float w = __expf(p);
        ss += w;
        a0 += w * v0;
        a1 += w * v1;
    }
    float2 bg2 = *(const float2*)(bias_gat + 2 * t2);
    float inv = 1.f / ss;
    float r0 = a0 * inv + bg2.x;
    float r1 = a1 * inv + bg2.y;

    float2 xv = *(const float2*)(x + (size_t)g * DIM + 2 * t2);
    float v0 = xv.x + r0, v1 = xv.y + r1;

    int wg = t2 >> 5, lane = t2 & 31;
    float s = v0 + v1;
#pragma unroll
    for (int o = 16; o >= 1; o >>= 1) s += __shfl_xor_sync(0xffffffffu, s, o);
    if (lane == 0) redS[gidx][wg] = s;
    __syncthreads();
    float mu = (redS[gidx][0] + redS[gidx][1]) * (1.f / DIM);
    float d0 = v0 - mu, d1 = v1 - mu;
    float q = d0 * d0 + d1 * d1;
#pragma unroll
    for (int o = 16; o >= 1; o >>= 1) q += __shfl_xor_sync(0xffffffffu, q, o);
    if (lane == 0) redQ[gidx][wg] = q;
    __syncthreads();
    float var = (redQ[gidx][0] + redQ[gidx][1]) * (1.f / DIM);
    float rstd = rsqrtf(var + 1e-5f);
    float2 gm = *(const float2*)(gamma + 2 * t2);
    float2 be = *(const float2*)(beta  + 2 * t2);
    float h0 = d0 * rstd * gm.x + be.x;
    float h1 = d1 * rstd * gm.y + be.y;
    *(float2*)(hout + (size_t)g * DIM + 2 * t2) = make_float2(h0, h1);
    __half2 hh; hh.x = __float2half(h0); hh.y = __float2half(h1);
    *(__half2*)(hhout + (size_t)g * DIM + 2 * t2) = hh;
}

// ---------------- LN2: out = LN(h + agg + agg2) ----------------
__global__ void k_ln3(const float* __restrict__ A, const float* __restrict__ B1,
                      const float* __restrict__ B2,
                      const float* __restrict__ gamma, const float* __restrict__ beta,
                      float* __restrict__ out)
{
    int g = blockIdx.x, t = threadIdx.x;
    size_t idx = (size_t)g * DIM + t;
    float v = A[idx] + B1[idx] + B2[idx];
    __shared__ float red[4];
    int lane = t & 31, w = t >> 5;
    float s = v;
#pragma unroll
    for (int o = 16; o >= 1; o >>= 1) s += __shfl_xor_sync(0xffffffffu, s, o);
    if (lane == 0) red[w] = s;
    __syncthreads();
    float mu = (red[0] + red[1] + red[2] + red[3]) * (1.f / DIM);
    float d = v - mu;
    float q = d * d;
#pragma unroll
    for (int o = 16; o >= 1; o >>= 1) q += __shfl_xor_sync(0xffffffffu, q, o);
    __syncthreads();
    if (lane == 0) red[w] = q;
    __syncthreads();
    float var = (red[0] + red[1] + red[2] + red[3]) * (1.f / DIM);
    out[idx] = d * rsqrtf(var + 1e-5f) * gamma[t] + beta[t];
}

// ---------------- launcher ----------------
extern "C" void kernel_launch(void* const* d_in, const int* in_sizes, int n_in,
                              void* d_out, int out_size)
{
    const float* x   = (const float*)d_in[0];
    const int*   ei  = (const int*)  d_in[1];
    const float* Wl  = (const float*)d_in[2];
    const float* bl  = (const float*)d_in[3];
    const float* Wr  = (const float*)d_in[4];
    const float* brv = (const float*)d_in[5];
    const float* att = (const float*)d_in[6];
    const float* bg  = (const float*)d_in[7];
    const float* W1  = (const float*)d_in[8];
    const float* b1  = (const float*)d_in[9];
    const float* W2  = (const float*)d_in[10];
    const float* b2  = (const float*)d_in[11];
    const float* g1  = (const float*)d_in[12];
    const float* be1 = (const float*)d_in[13];
    const float* g2  = (const float*)d_in[14];
    const float* be2 = (const float*)d_in[15];
    float* out = (float*)d_out;

    int E = in_sizes[1] / 2;
    if (E > EMAX) E = EMAX;

    cudaFuncSetAttribute(mmagemm, cudaFuncAttributeMaxDynamicSharedMemorySize, GSMEM);

    void *pagg, *pagg2, *ph, *phb, *pff1, *pxb, *pwlrt, *pw1t, *pw2t, *pblr;
    cudaGetSymbolAddress(&pagg,  g_agg);
    cudaGetSymbolAddress(&pagg2, g_agg2);
    cudaGetSymbolAddress(&ph,    g_h);
    cudaGetSymbolAddress(&phb,   g_hb);
    cudaGetSymbolAddress(&pff1,  g_ff1);
    cudaGetSymbolAddress(&pxb,   g_xb);
    cudaGetSymbolAddress(&pwlrt, g_wlrt);
    cudaGetSymbolAddress(&pw1t,  g_w1t);
    cudaGetSymbolAddress(&pw2t,  g_w2t);
    cudaGetSymbolAddress(&pblr,  g_blr);

    __half* xb   = (__half*)pxb;
    __half* wlrt = (__half*)pwlrt;
    __half* w1t  = (__half*)pw1t;
    __half* w2t  = (__half*)pw2t;
    __half* hh   = (__half*)phb;
    __half* xlr  = (__half*)pff1;       // [TOT,256] fp16, dead after k_edge_ln1
    __half* ff1  = (__half*)pff1;       // [TOT,2048] fp16, written after xlr dead

    const int GM = (TOT + 127) / 128;   // 663
    const long NCVT = (long)TOT * DIM / 4 + 2L * DIM * DIM + 2L * DIM * FFD + 256;
    const int GCVT = (int)((NCVT + 255) / 256);
    int gE = (E + 255) / 256;

    // 1-2: edge decode + degree histogram
    k_init_detect<<<gE, 256>>>(ei, E);
    k_decode_hist<<<gE, 256>>>(ei, E);
    // 3: all conversions
    k_cvt_all<<<GCVT, 256>>>(x, Wl, Wr, W1, W2, bl, brv);
    // 4: [x_l | x_r] = x @ [Wl|Wr] + [bl|br]
    mmagemm<<<dim3(GM, 2, 1), 256, GSMEM>>>(xb, wlrt, (const float*)pblr,
        nullptr, nullptr, xlr, TOT, 256, DIM, DIM, DIM, 0);
    // 5-6: CSR finalize
    k_scan<<<1, 1024>>>();
    k_scatter<<<(E + NB + 255) / 256, 256>>>(E);
    // 7: GATv2 aggregation + LN1 fused -> h (fp32 + fp16)
    k_edge_ln1<<<dim3(NB, BTI / 4), 256>>>(xlr, x, att, bg, g1, be1, (float*)ph, hh);
    // 8: ff1 = relu(h@W1 + b1) -> fp16
    mmagemm<<<dim3(GM, 16, 1), 256, GSMEM>>>(hh, w1t, b1,
        nullptr, nullptr, ff1, TOT, FFD, DIM, DIM, DIM, 1);
    // 9: ffn = ff1@W2 + b2, split-K fused in one launch (z selects K-half)
    mmagemm<<<dim3(GM, 1, 2), 256, GSMEM>>>(ff1, w2t, b2,
        (float*)pagg, (float*)pagg2, nullptr, TOT, DIM, 1024, FFD, FFD, 0);
    // 10: out = LN2(h + ffn halves)
    k_ln3<<<TOT, 128>>>((const float*)ph, (const float*)pagg, (const float*)pagg2,
                        g2, be2, out);
}

// round 11
// speedup vs baseline: 1.7542x; 1.1137x over previous
#include <cuda_runtime.h>
#include <cuda_fp16.h>
#include <cstdint>

// ---------------- problem constants ----------------
#define NB    883
#define BTI   96
#define TOT   (NB*BTI)       // 84768
#define DIM   128
#define FFD   2048
#define EMAX  7168

// ---------------- device scratch ----------------
__device__ float g_agg [(size_t)TOT*DIM];
__device__ float g_agg2[(size_t)TOT*DIM];
__device__ float g_h  [(size_t)TOT*DIM];
__device__ __half g_hb [(size_t)TOT*DIM];    // h fp16
__device__ float g_ff1[(size_t)TOT*FFD/2];   // xlr fp16 (TOT*256) early; ff1 fp16 (TOT*2048) later
__device__ __half g_xb [(size_t)TOT*DIM];    // x fp16
__device__ __half g_wlrt[256*DIM];           // [Wl;Wr] transposed: [256, 128]
__device__ __half g_w1t[(size_t)FFD*DIM];    // W1^T [2048,128]
__device__ __half g_w2t[(size_t)DIM*FFD];    // W2^T [128,2048]
__device__ float  g_blr[256];

__device__ int g_src[EMAX];
__device__ int g_dst[EMAX];
__device__ int g_deg[NB];
__device__ int g_rowptr[NB+1];
__device__ int g_wp[NB];
__device__ int g_csr[EMAX+NB];
__device__ int g_flag;   // sticky across replays: OR-idempotent => deterministic

// ---------------- helpers ----------------
__device__ __forceinline__ uint32_t smem_u32(const void* p) {
    uint32_t a;
    asm("{ .reg .u64 t; cvta.to.shared.u64 t, %1; cvt.u32.u64 %0, t; }" : "=r"(a) : "l"(p));
    return a;
}
__device__ __forceinline__ void cp16(uint32_t s, const void* g) {
    asm volatile("cp.async.cg.shared.global [%0], [%1], 16;" :: "r"(s), "l"(g));
}
#define CP_COMMIT() asm volatile("cp.async.commit_group;" ::: "memory")
#define CP_WAIT1()  asm volatile("cp.async.wait_group 1;" ::: "memory")

__device__ __forceinline__ void ldm4(uint32_t* r, uint32_t addr) {
    asm volatile("ldmatrix.sync.aligned.m8n8.x4.shared.b16 {%0,%1,%2,%3}, [%4];"
        : "=r"(r[0]), "=r"(r[1]), "=r"(r[2]), "=r"(r[3]) : "r"(addr));
}
__device__ __forceinline__ void mma16816(float* d, const uint32_t* a, const uint32_t* b) {
    asm volatile(
        "mma.sync.aligned.m16n8k16.row.col.f32.f16.f16.f32 "
        "{%0,%1,%2,%3}, {%4,%5,%6,%7}, {%8,%9}, {%0,%1,%2,%3};"
        : "+f"(d[0]), "+f"(d[1]), "+f"(d[2]), "+f"(d[3])
        : "r"(a[0]), "r"(a[1]), "r"(a[2]), "r"(a[3]), "r"(b[0]), "r"(b[1]));
}

// ==================================================================================
// gemmA: K=128 fixed. A tile resident in smem; block streams `nper` N tiles of B
// (double-buffered). 256 threads, 8 warps of 32x64, 2 CTA/SM. fp16 output + bias.
// ==================================================================================
#define AROWB  272                   // 256B data + 16B pad (row stride mod 128 = 16)
#define ATILE  (128*AROWB)           // 34816
#define GSMEMA (3*ATILE)             // 104448: A + 2 B buffers

__global__ void __launch_bounds__(256, 2) gemmA(
    const __half* __restrict__ A, const __half* __restrict__ Bm,
    const float* __restrict__ bias, __half* __restrict__ Oh,
    int M, int Ntot, int nper, int relu)
{
    extern __shared__ char smem[];
    const uint32_t sb = smem_u32(smem);
    const int tid = threadIdx.x;
    const int lane = tid & 31, wid = tid >> 5;
    const int wm = wid & 3, wn = wid >> 2;       // 4x2 warp grid, 32x64 tiles
    const int bm = blockIdx.x * 128;
    const int nb0 = blockIdx.y * nper;

    // prologue: A tile + B(0), one group
    {
#pragma unroll
        for (int j = 0; j < 8; j++) {
            int id = tid + 256 * j;
            int row = id >> 4, col = id & 15;
            cp16(sb + row * AROWB + col * 16,
                 A + (size_t)min(bm + row, M - 1) * DIM + col * 8);
        }
        int cb = nb0 * 128;
#pragma unroll
        for (int j = 0; j < 8; j++) {
            int id = tid + 256 * j;
            int row = id >> 4, col = id & 15;
            cp16(sb + ATILE + row * AROWB + col * 16,
                 Bm + (size_t)(cb + row) * DIM + col * 8);
        }
        CP_COMMIT();
    }

    const uint32_t aoff = (uint32_t)((wm * 32 + (lane & 15)) * AROWB + ((lane >> 4) * 16));
    const uint32_t boff = (uint32_t)((wn * 64 + (lane & 7) + ((lane >> 4) << 3)) * AROWB
                                     + (((lane >> 3) & 1) * 16));

    float acc[2][8][4];
#pragma unroll
    for (int mi = 0; mi < 2; mi++)
#pragma unroll
        for (int ni = 0; ni < 8; ni++)
#pragma unroll
            for (int q = 0; q < 4; q++) acc[mi][ni][q] = 0.f;

    for (int nt = 0; nt < nper; nt++) {
        // prefetch B(nt+1) into the other buffer (protected by previous trailing sync)
        if (nt + 1 < nper) {
            int cb = (nb0 + nt + 1) * 128;
            uint32_t bb = sb + ATILE + ((nt + 1) & 1) * ATILE;
#pragma unroll
            for (int j = 0; j < 8; j++) {
                int id = tid + 256 * j;
                int row = id >> 4, col = id & 15;
                cp16(bb + row * AROWB + col * 16,
                     Bm + (size_t)(cb + row) * DIM + col * 8);
            }
        }
        CP_COMMIT();
        CP_WAIT1();              // newest group = B(nt+1) -> A and B(nt) resident
        __syncthreads();

        uint32_t sB = sb + ATILE + (nt & 1) * ATILE;
#pragma unroll
        for (int kk = 0; kk < 8; kk++) {
            uint32_t kb = kk * 32;
            uint32_t af[2][4], bf[4][4];
#pragma unroll
            for (int mi = 0; mi < 2; mi++)
                ldm4(af[mi], sb + aoff + mi * (16 * AROWB) + kb);
#pragma unroll
            for (int p = 0; p < 4; p++)
                ldm4(bf[p], sB + boff + p * (16 * AROWB) + kb);
#pragma unroll
            for (int mi = 0; mi < 2; mi++)
#pragma unroll
                for (int ni = 0; ni < 8; ni++)
                    mma16816(acc[mi][ni], af[mi], &bf[ni >> 1][(ni & 1) * 2]);
        }

        // epilogue for this N tile (regs + global only)
        int cb = (nb0 + nt) * 128;
#pragma unroll
        for (int mi = 0; mi < 2; mi++) {
#pragma unroll
            for (int ni = 0; ni < 8; ni++) {
                int row0 = bm + wm * 32 + mi * 16 + (lane >> 2);
                int col  = cb + wn * 64 + ni * 8 + (lane & 3) * 2;
                float b0 = __ldg(bias + col), b1 = __ldg(bias + col + 1);
#pragma unroll
                for (int half_ = 0; half_ < 2; half_++) {
                    int row = row0 + half_ * 8;
                    if (row < M) {
                        float v0 = acc[mi][ni][half_ * 2 + 0] + b0;
                        float v1 = acc[mi][ni][half_ * 2 + 1] + b1;
                        if (relu) { v0 = fmaxf(v0, 0.f); v1 = fmaxf(v1, 0.f); }
                        __half2 hh; hh.x = __float2half(v0); hh.y = __float2half(v1);
                        *(__half2*)(Oh + (size_t)row * Ntot + col) = hh;
                    }
                }
#pragma unroll
                for (int q = 0; q < 4; q++) acc[mi][ni][q] = 0.f;
            }
        }
        __syncthreads();         // protect buffer nt&1 before iter nt+1 prefetch
    }
}

// ==================================================================================
// gemmK: K-streaming (K mult of 64). BK=64, 3 stages, ONE barrier per iteration.
// 256 threads, 8 warps of 32x64, 2 CTA/SM. fp32 output.
// gridDim.z==2 => split-K: z=0 -> C (+bias), z=1 -> C2 (no bias).
// ==================================================================================
#define SROWB   144
#define ARRB    (128*SROWB)          // 18432
#define STAGEB  (2*ARRB)             // 36864
#define GSMEMK  (3*STAGEB)           // 110592

__global__ void __launch_bounds__(256, 2) gemmK(
    const __half* __restrict__ A, const __half* __restrict__ B,
    const float* __restrict__ bias, float* __restrict__ C, float* __restrict__ C2,
    int M, int N, int K, int lda, int ldb)
{
    extern __shared__ char smem[];
    const uint32_t sb = smem_u32(smem);
    const int tid = threadIdx.x;
    const int lane = tid & 31, wid = tid >> 5;
    const int wm = wid & 3, wn = wid >> 2;
    const int bm = blockIdx.x * 128, bn = blockIdx.y * 128;
    const int nk = K >> 6;

    if (blockIdx.z) {                             // split-K
        A += (size_t)blockIdx.z * K;
        B += (size_t)blockIdx.z * K;
        C = C2;
        bias = nullptr;
    }

    auto load_stage = [&](int st, int kc) {
        int k0 = kc << 6;
        uint32_t base = sb + st * STAGEB;
#pragma unroll
        for (int j = 0; j < 8; j++) {
            int id = tid + 256 * j;
            int arr = id >> 10;
            int c = id & 1023;
            int row = c >> 3, col = c & 7;
            const __half* g;
            if (arr == 0) g = A + (size_t)min(bm + row, M - 1) * lda + k0 + col * 8;
            else          g = B + (size_t)(bn + row) * ldb + k0 + col * 8;
            cp16(base + arr * ARRB + row * SROWB + col * 16, g);
        }
        CP_COMMIT();
    };

    float acc[2][8][4];
#pragma unroll
    for (int mi = 0; mi < 2; mi++)
#pragma unroll
        for (int ni = 0; ni < 8; ni++)
#pragma unroll
            for (int q = 0; q < 4; q++) acc[mi][ni][q] = 0.f;

    const uint32_t aoff = (uint32_t)((wm * 32 + (lane & 15)) * SROWB + ((lane >> 4) * 16));
    const uint32_t boff = (uint32_t)((wn * 64 + (lane & 7) + ((lane >> 4) << 3)) * SROWB
                                     + (((lane >> 3) & 1) * 16));

    load_stage(0, 0);
    load_stage(1, 1);

    for (int c = 0; c < nk; c++) {
        CP_WAIT1();
        __syncthreads();         // stage c visible to all; all warps done with (c-1)
        if (c + 2 < nk) load_stage((c + 2) % 3, c + 2);   // (c+2)%3 == (c-1)%3, safe
        else CP_COMMIT();

        uint32_t s = sb + (c % 3) * STAGEB;
        uint32_t sA = s, sB = s + ARRB;
#pragma unroll
        for (int kk = 0; kk < 4; kk++) {
            uint32_t kb = kk * 32;
            uint32_t af[2][4], bf[4][4];
#pragma unroll
            for (int mi = 0; mi < 2; mi++)
                ldm4(af[mi], sA + aoff + mi * (16 * SROWB) + kb);
#pragma unroll
            for (int p = 0; p < 4; p++)
                ldm4(bf[p], sB + boff + p * (16 * SROWB) + kb);
#pragma unroll
            for (int mi = 0; mi < 2; mi++)
#pragma unroll
                for (int ni = 0; ni < 8; ni++)
                    mma16816(acc[mi][ni], af[mi], &bf[ni >> 1][(ni & 1) * 2]);
        }
    }

    // epilogue (fp32)
#pragma unroll
    for (int mi = 0; mi < 2; mi++) {
#pragma unroll
        for (int ni = 0; ni < 8; ni++) {
            int row0 = bm + wm * 32 + mi * 16 + (lane >> 2);
            int col  = bn + wn * 64 + ni * 8 + (lane & 3) * 2;
            float b0 = bias ? __ldg(bias + col)     : 0.f;
            float b1 = bias ? __ldg(bias + col + 1) : 0.f;
#pragma unroll
            for (int half_ = 0; half_ < 2; half_++) {
                int row = row0 + half_ * 8;
                if (row >= M) continue;
                float v0 = acc[mi][ni][half_ * 2 + 0] + b0;
                float v1 = acc[mi][ni][half_ * 2 + 1] + b1;
                *(float2*)(C + (size_t)row * N + col) = make_float2(v0, v1);
            }
        }
    }
}

// ---------------- merged prelude kernels ----------------
__global__ void k_init_detect(const int* __restrict__ w, int E) {
    int k = blockIdx.x * blockDim.x + threadIdx.x;
    if (k < NB) g_deg[k] = 1;                     // self loop
    if (k < E && w[2 * k + 1] != 0) atomicOr(&g_flag, 1);
}
__global__ void k_decode_hist(const int* __restrict__ w, int E) {
    int k = blockIdx.x * blockDim.x + threadIdx.x;
    if (k >= E) return;
    int s, d;
    if (g_flag == 0) { s = w[2 * k]; d = w[2 * (E + k)]; }
    else             { s = w[k];     d = w[E + k]; }
    g_src[k] = s;
    g_dst[k] = d;
    atomicAdd(&g_deg[d], 1);
}
__global__ void k_cvt_all(const float* __restrict__ x,
                          const float* __restrict__ Wl, const float* __restrict__ Wr,
                          const float* __restrict__ W1, const float* __restrict__ W2,
                          const float* __restrict__ bl, const float* __restrict__ br)
{
    const long N0 = (long)TOT * DIM / 4;
    long id = (long)blockIdx.x * blockDim.x + threadIdx.x;
    if (id < N0) {
        float4 v = ((const float4*)x)[id];
        long s = id * 4;
        __half2 a; a.x = __float2half(v.x); a.y = __float2half(v.y);
        __half2 b; b.x = __float2half(v.z); b.y = __float2half(v.w);
        *(__half2*)(g_xb + s)     = a;
        *(__half2*)(g_xb + s + 2) = b;
        return;
    }
    id -= N0;
    if (id < DIM * DIM) {
        int k = (int)id / DIM, n = (int)id % DIM;
        g_wlrt[(size_t)n * DIM + k] = __float2half(Wl[id]);
        return;
    }
    id -= DIM * DIM;
    if (id < DIM * DIM) {
        int k = (int)id / DIM, n = (int)id % DIM;
        g_wlrt[(size_t)(128 + n) * DIM + k] = __float2half(Wr[id]);
        return;
    }
    id -= DIM * DIM;
    if (id < (long)DIM * FFD) {
        int k = (int)(id / FFD), n = (int)(id % FFD);
        g_w1t[(size_t)n * DIM + k] = __float2half(W1[id]);
        return;
    }
    id -= (long)DIM * FFD;
    if (id < (long)DIM * FFD) {
        int k = (int)(id / DIM), n = (int)(id % DIM);
        g_w2t[(size_t)n * FFD + k] = __float2half(W2[id]);
        return;
    }
    id -= (long)DIM * FFD;
    if (id < 256) {
        g_blr[id] = (id < 128) ? bl[id] : br[id - 128];
    }
}

__global__ void k_scan() {
    __shared__ int s[1024];
    int t = threadIdx.x;
    int v = (t < NB) ? g_deg[t] : 0;
    s[t] = v;
    __syncthreads();
    for (int off = 1; off < 1024; off <<= 1) {
        int u = (t >= off) ? s[t - off] : 0;
        __syncthreads();
        s[t] += u;
        __syncthreads();
    }
    if (t < NB) { g_rowptr[t + 1] = s[t]; g_wp[t] = s[t] - v; }
    if (t == 0) g_rowptr[0] = 0;
}
__global__ void k_scatter(int E) {
    int j = blockIdx.x * blockDim.x + threadIdx.x;
    if (j >= E + NB) return;
    int s, d;
    if (j < E) { s = g_src[j]; d = g_dst[j]; }
    else       { s = d = j - E; }
    g_csr[atomicAdd(&g_wp[d], 1)] = s;
}

// ---------------- fused GATv2 edge aggregation + LN1 ----------------
__global__ void __launch_bounds__(256) k_edge_ln1(
    const __half* __restrict__ xlr, const float* __restrict__ x,
    const float* __restrict__ att, const float* __restrict__ bias_gat,
    const float* __restrict__ gamma, const float* __restrict__ beta,
    float* __restrict__ hout, __half* __restrict__ hhout)
{
    __shared__ float redS[4][2], redQ[4][2];
    const int i = blockIdx.x;
    const int gidx = threadIdx.x >> 6;
    const int t2 = threadIdx.x & 63;
    const int b = blockIdx.y * 4 + gidx;
    const int g = b * NB + i;
    const int base = b * NB;

    float2 attv = *(const float2*)(att + 2 * t2);
    __half2 rx2 = *(const __half2*)(xlr + (size_t)g * 256 + 128 + 2 * t2);
    float rx0 = __half2float(rx2.x), rx1 = __half2float(rx2.y);

    const int e0 = g_rowptr[i], e1 = g_rowptr[i + 1];
    float ss = 0.f, a0 = 0.f, a1 = 0.f;
#pragma unroll 2
    for (int e = e0; e < e1; e++) {
        int sg = base + g_csr[e];
        __half2 v2 = *(const __half2*)(xlr + (size_t)sg * 256 + 2 * t2);
        float v0 = __half2float(v2.x), v1 = __half2float(v2.y);
        float e0f = v0 + rx0, e1f = v1 + rx1;
        e0f = e0f > 0.f ? e0f : 0.2f * e0f;
        e1f = e1f > 0.f ? e1f : 0.2f * e1f;
        float p = e0f * attv.x + e1f * attv.y;
        p += __shfl_xor_sync(0xffffffffu, p, 4, 8);
        p += __shfl_xor_sync(0xffffffffu, p, 2, 8);
        p += __shfl_xor_sync(0xffffffffu, p, 1, 8);
        float w = __expf(p);
        ss += w;
        a0 += w * v0;
        a1 += w * v1;
    }
    float2 bg2 = *(const float2*)(bias_gat + 2 * t2);
    float inv = 1.f / ss;
    float r0 = a0 * inv + bg2.x;
    float r1 = a1 * inv + bg2.y;

    float2 xv = *(const float2*)(x + (size_t)g * DIM + 2 * t2);
    float v0 = xv.x + r0, v1 = xv.y + r1;

    int wg = t2 >> 5, lane = t2 & 31;
    float s = v0 + v1;
#pragma unroll
    for (int o = 16; o >= 1; o >>= 1) s += __shfl_xor_sync(0xffffffffu, s, o);
    if (lane == 0) redS[gidx][wg] = s;
    __syncthreads();
    float mu = (redS[gidx][0] + redS[gidx][1]) * (1.f / DIM);
    float d0 = v0 - mu, d1 = v1 - mu;
    float q = d0 * d0 + d1 * d1;
#pragma unroll
    for (int o = 16; o >= 1; o >>= 1) q += __shfl_xor_sync(0xffffffffu, q, o);
    if (lane == 0) redQ[gidx][wg] = q;
    __syncthreads();
    float var = (redQ[gidx][0] + redQ[gidx][1]) * (1.f / DIM);
    float rstd = rsqrtf(var + 1e-5f);
    float2 gm = *(const float2*)(gamma + 2 * t2);
    float2 be = *(const float2*)(beta  + 2 * t2);
    float h0 = d0 * rstd * gm.x + be.x;
    float h1 = d1 * rstd * gm.y + be.y;
    *(float2*)(hout + (size_t)g * DIM + 2 * t2) = make_float2(h0, h1);
    __half2 hh; hh.x = __float2half(h0); hh.y = __float2half(h1);
    *(__half2*)(hhout + (size_t)g * DIM + 2 * t2) = hh;
}

// ---------------- LN2: out = LN(h + agg + agg2) ----------------
__global__ void k_ln3(const float* __restrict__ A, const float* __restrict__ B1,
                      const float* __restrict__ B2,
                      const float* __restrict__ gamma, const float* __restrict__ beta,
                      float* __restrict__ out)
{
    int g = blockIdx.x, t = threadIdx.x;
    size_t idx = (size_t)g * DIM + t;
    float v = A[idx] + B1[idx] + B2[idx];
    __shared__ float red[4];
    int lane = t & 31, w = t >> 5;
    float s = v;
#pragma unroll
    for (int o = 16; o >= 1; o >>= 1) s += __shfl_xor_sync(0xffffffffu, s, o);
    if (lane == 0) red[w] = s;
    __syncthreads();
    float mu = (red[0] + red[1] + red[2] + red[3]) * (1.f / DIM);
    float d = v - mu;
    float q = d * d;
#pragma unroll
    for (int o = 16; o >= 1; o >>= 1) q += __shfl_xor_sync(0xffffffffu, q, o);
    __syncthreads();
    if (lane == 0) red[w] = q;
    __syncthreads();
    float var = (red[0] + red[1] + red[2] + red[3]) * (1.f / DIM);
    out[idx] = d * rsqrtf(var + 1e-5f) * gamma[t] + beta[t];
}

// ---------------- launcher ----------------
extern "C" void kernel_launch(void* const* d_in, const int* in_sizes, int n_in,
                              void* d_out, int out_size)
{
    const float* x   = (const float*)d_in[0];
    const int*   ei  = (const int*)  d_in[1];
    const float* Wl  = (const float*)d_in[2];
    const float* bl  = (const float*)d_in[3];
    const float* Wr  = (const float*)d_in[4];
    const float* brv = (const float*)d_in[5];
    const float* att = (const float*)d_in[6];
    const float* bg  = (const float*)d_in[7];
    const float* W1  = (const float*)d_in[8];
    const float* b1  = (const float*)d_in[9];
    const float* W2  = (const float*)d_in[10];
    const float* b2  = (const float*)d_in[11];
    const float* g1  = (const float*)d_in[12];
    const float* be1 = (const float*)d_in[13];
    const float* g2  = (const float*)d_in[14];
    const float* be2 = (const float*)d_in[15];
    float* out = (float*)d_out;

    int E = in_sizes[1] / 2;
    if (E > EMAX) E = EMAX;

    cudaFuncSetAttribute(gemmA, cudaFuncAttributeMaxDynamicSharedMemorySize, GSMEMA);
    cudaFuncSetAttribute(gemmK, cudaFuncAttributeMaxDynamicSharedMemorySize, GSMEMK);

    void *pagg, *pagg2, *ph, *phb, *pff1, *pxb, *pwlrt, *pw1t, *pw2t, *pblr;
    cudaGetSymbolAddress(&pagg,  g_agg);
    cudaGetSymbolAddress(&pagg2, g_agg2);
    cudaGetSymbolAddress(&ph,    g_h);
    cudaGetSymbolAddress(&phb,   g_hb);
    cudaGetSymbolAddress(&pff1,  g_ff1);
    cudaGetSymbolAddress(&pxb,   g_xb);
    cudaGetSymbolAddress(&pwlrt, g_wlrt);
    cudaGetSymbolAddress(&pw1t,  g_w1t);
    cudaGetSymbolAddress(&pw2t,  g_w2t);
    cudaGetSymbolAddress(&pblr,  g_blr);

    __half* xb   = (__half*)pxb;
    __half* wlrt = (__half*)pwlrt;
    __half* w1t  = (__half*)pw1t;
    __half* w2t  = (__half*)pw2t;
    __half* hh   = (__half*)phb;
    __half* xlr  = (__half*)pff1;       // [TOT,256] fp16, dead after k_edge_ln1
    __half* ff1  = (__half*)pff1;       // [TOT,2048] fp16, written after xlr dead

    const int GM = (TOT + 127) / 128;   // 663
    const long NCVT = (long)TOT * DIM / 4 + 2L * DIM * DIM + 2L * DIM * FFD + 256;
    const int GCVT = (int)((NCVT + 255) / 256);
    int gE = (E + 255) / 256;

    // 1-2: edge decode + degree histogram
    k_init_detect<<<gE, 256>>>(ei, E);
    k_decode_hist<<<gE, 256>>>(ei, E);
    // 3: all conversions
    k_cvt_all<<<GCVT, 256>>>(x, Wl, Wr, W1, W2, bl, brv);
    // 4: [x_l | x_r] = x @ [Wl|Wr] + [bl|br]  (A-resident, nper=1)
    gemmA<<<dim3(GM, 2), 256, GSMEMA>>>(xb, wlrt, (const float*)pblr,
        xlr, TOT, 256, 1, 0);
    // 5-6: CSR finalize
    k_scan<<<1, 1024>>>();
    k_scatter<<<(E + NB + 255) / 256, 256>>>(E);
    // 7: GATv2 aggregation + LN1 fused -> h (fp32 + fp16)
    k_edge_ln1<<<dim3(NB, BTI / 4), 256>>>(xlr, x, att, bg, g1, be1, (float*)ph, hh);
    // 8: ff1 = relu(h@W1 + b1) -> fp16 (A-resident, 8 N tiles per block)
    gemmA<<<dim3(GM, 2), 256, GSMEMA>>>(hh, w1t, b1,
        ff1, TOT, FFD, 8, 1);
    // 9: ffn = ff1@W2 + b2, split-K fused in one launch (z selects K-half)
    gemmK<<<dim3(GM, 1, 2), 256, GSMEMK>>>(ff1, w2t, b2,
        (float*)pagg, (float*)pagg2, TOT, DIM, 1024, FFD, FFD);
    // 10: out = LN2(h + ffn halves)
    k_ln3<<<TOT, 128>>>((const float*)ph, (const float*)pagg, (const float*)pagg2,
                        g2, be2, out);
}